// round 15
// baseline (speedup 1.0000x reference)
#include <cuda_runtime.h>
#include <cstdint>

// Submanifold sparse conv — compacted per-offset gather-GEMM.
//  zero_kernel   : reset per-k counters
//  fused_kernel  : blocks [0,CEN_BLOCKS) -> center GEMM (out = bias + F@W13);
//                  rest -> element-parallel compaction.
//  taps_kernel   : out[site] += F[nb] @ W[k]; W[k] in 32 f32 regs; cp.async
//                  ring (4 quad buffers, 3 in flight), 1 syncwarp/iter,
//                  coalesced per-lane atomicAdd epilogue. 4 blocks/SM.

#define C 32
#define KTAPS 27
#define KCENTER 13
#define NCAP 131072

__device__ int  g_count[KTAPS];
__device__ int2 g_list[KTAPS * NCAP];

typedef unsigned long long u64;

__device__ __forceinline__ u64 fma_f32x2(u64 a, u64 b, u64 c)
{
    u64 d;
    asm("fma.rn.f32x2 %0, %1, %2, %3;" : "=l"(d) : "l"(a), "l"(b), "l"(c));
    return d;
}
__device__ __forceinline__ u64 pack_f32x2(float lo, float hi)
{
    u64 d;
    asm("mov.b64 %0, {%1, %2};" : "=l"(d) : "f"(lo), "f"(hi));
    return d;
}
__device__ __forceinline__ float sum_f32x2(u64 v)
{
    float lo, hi;
    asm("mov.b64 {%0, %1}, %2;" : "=f"(lo), "=f"(hi) : "l"(v));
    return lo + hi;
}
__device__ __forceinline__ void cp_async4(uint32_t saddr, const float* gptr)
{
    asm volatile("cp.async.ca.shared.global [%0], [%1], 4;"
                 :: "r"(saddr), "l"(gptr) : "memory");
}
__device__ __forceinline__ void cp_commit()
{
    asm volatile("cp.async.commit_group;" ::: "memory");
}
template <int N>
__device__ __forceinline__ void cp_wait()
{
    asm volatile("cp.async.wait_group %0;" :: "n"(N) : "memory");
}

// ---------------------------------------------------------------- zero
__global__ void zero_kernel()
{
    if (threadIdx.x < KTAPS) g_count[threadIdx.x] = 0;
}

// ---------------------------------------------------------------- fused center + compact
#define FB_THREADS 256
#define CEN_BLOCKS 592
#define CB_EPT 8
#define CB_ELEMS (FB_THREADS * CB_EPT)

__global__ void __launch_bounds__(FB_THREADS)
fused_kernel(const float* __restrict__ features,
             const float* __restrict__ weight,
             const float* __restrict__ bias,
             const int*   __restrict__ nbr_idx,
             const int*   __restrict__ nbr_mask,
             float* __restrict__ out,
             int n_sites, int n_elems)
{
    __shared__ union {
        struct { int scount[KTAPS]; int sbase[KTAPS]; } cp;
        float rows[FB_THREADS / 32][C];
    } sm;

    const int tid  = threadIdx.x;
    const int lane = tid & 31;
    const int wib  = tid >> 5;

    if (blockIdx.x < CEN_BLOCKS) {
        // ---------------- center GEMM ----------------
        u64 w2[C / 2];
        const float* w13 = weight + KCENTER * C * C;
        #pragma unroll
        for (int g = 0; g < C / 2; ++g)
            w2[g] = pack_f32x2(w13[(2 * g) * C + lane], w13[(2 * g + 1) * C + lane]);

        const float my_bias = bias[lane];
        float* row = sm.rows[wib];

        const int gwarp  = blockIdx.x * (FB_THREADS / 32) + wib;
        const int nwarps = CEN_BLOCKS * (FB_THREADS / 32);

        float fvA = 0.f;
        if (gwarp < n_sites) fvA = features[gwarp * C + lane];

        for (int site = gwarp; site < n_sites; site += nwarps) {
            const int nsite = site + nwarps;
            float fvB = 0.f;
            if (nsite < n_sites) fvB = features[nsite * C + lane];

            row[lane] = fvA;
            __syncwarp();

            u64 ta = 0ull, tb = 0ull;
            #pragma unroll
            for (int g = 0; g < 8; ++g) {
                const ulonglong2 fp = *reinterpret_cast<const ulonglong2*>(row + (g << 2));
                ta = fma_f32x2(fp.x, w2[2 * g + 0], ta);
                tb = fma_f32x2(fp.y, w2[2 * g + 1], tb);
            }
            __syncwarp();

            out[site * C + lane] = my_bias + sum_f32x2(ta) + sum_f32x2(tb);
            fvA = fvB;
        }
    } else {
        // ---------------- compaction (coalesced) ----------------
        if (tid < KTAPS) sm.cp.scount[tid] = 0;
        __syncthreads();

        const int base = (blockIdx.x - CEN_BLOCKS) * CB_ELEMS;
        bool act[CB_EPT];

        #pragma unroll
        for (int s = 0; s < CB_EPT; ++s) {
            const int e = base + s * FB_THREADS + tid;
            bool a = false;
            if (e < n_elems) {
                const int k = e % KTAPS;
                a = (k != KCENTER) && (nbr_mask[e] != 0);
                if (a) atomicAdd(&sm.cp.scount[k], 1);
            }
            act[s] = a;
        }
        __syncthreads();

        if (tid < KTAPS) {
            const int c = sm.cp.scount[tid];
            sm.cp.sbase[tid]  = c ? atomicAdd(&g_count[tid], c) : 0;
            sm.cp.scount[tid] = 0;
        }
        __syncthreads();

        #pragma unroll
        for (int s = 0; s < CB_EPT; ++s) {
            if (act[s]) {
                const int e    = base + s * FB_THREADS + tid;
                const int site = e / KTAPS;
                const int k    = e - site * KTAPS;
                const int pos  = sm.cp.sbase[k] + atomicAdd(&sm.cp.scount[k], 1);
                g_list[k * NCAP + pos] = make_int2(site, nbr_idx[e]);
            }
        }
    }
}

// ---------------------------------------------------------------- taps
#define PB_WARPS 8
#define PB_THREADS 256
#define PB_BLOCKS_X 22      // 26*22 = 572 blocks ~= one wave at 4 blocks/SM
#define BUFS 4              // quad buffers (ring)
#define INFLIGHT 3          // cp.async groups outstanding

__global__ void __launch_bounds__(PB_THREADS, 4)
taps_kernel(const float* __restrict__ features,
            const float* __restrict__ weight,
            float* __restrict__ out)
{
    __shared__ float rows[PB_WARPS][BUFS * 4][C];   // 16 KB

    int k = blockIdx.y;
    if (k >= KCENTER) ++k;

    const int tid  = threadIdx.x;
    const int lane = tid & 31;
    const int wib  = tid >> 5;

    // W[k][ci][lane] in 32 f32 registers
    float w[C];
    const float* wkp = weight + k * C * C;
    #pragma unroll
    for (int ci = 0; ci < C; ++ci)
        w[ci] = wkp[ci * C + lane];

    const int cnt    = g_count[k];
    const int nquads = cnt >> 2;
    const int warps_per_k = gridDim.x * PB_WARPS;
    const int wid_in_k = blockIdx.x * PB_WARPS + wib;
    const int chunk = (nquads + warps_per_k - 1) / warps_per_k;
    const int q0   = wid_in_k * chunk;
    const int qend = min(q0 + chunk, nquads);

    const int4* list4 = reinterpret_cast<const int4*>(g_list + k * NCAP);
    const uint32_t rowbase =
        (uint32_t)__cvta_generic_to_shared(&rows[wib][0][0]);

    // issue gathers for quad q into ring buffer (q & 3)
    auto issue_quad = [&](int4 e0, int4 e1, int buf) {
        const uint32_t d = rowbase + (((buf << 2) * C) + lane) * 4u;
        cp_async4(d + 0 * C * 4u, features + (size_t)e0.y * C + lane);
        cp_async4(d + 1 * C * 4u, features + (size_t)e0.w * C + lane);
        cp_async4(d + 2 * C * 4u, features + (size_t)e1.y * C + lane);
        cp_async4(d + 3 * C * 4u, features + (size_t)e1.w * C + lane);
        cp_commit();
    };

    if (q0 < qend) {
        // ---- prologue: 3 groups in flight ----
        #pragma unroll
        for (int i = 0; i < INFLIGHT; ++i) {
            if (q0 + i < qend)
                issue_quad(list4[2 * (q0 + i)], list4[2 * (q0 + i) + 1], i & (BUFS - 1));
            else
                cp_commit();
        }

        // entry prefetch for quad q0+INFLIGHT
        int4 en0 = make_int4(0, 0, 0, 0), en1 = en0;
        if (q0 + INFLIGHT < qend) {
            en0 = list4[2 * (q0 + INFLIGHT)];
            en1 = list4[2 * (q0 + INFLIGHT) + 1];
        }

        for (int q = q0; q < qend; ++q) {
            const int buf = (q - q0) & (BUFS - 1);

            cp_wait<INFLIGHT - 1>();   // quad q resident
            __syncwarp();

            // sites re-read from L1-hot list (cheap, avoids smem staging race)
            const int4 e0 = list4[2 * q];
            const int4 e1 = list4[2 * q + 1];

            const float* r0 = rows[wib][(buf << 2) + 0];
            const float* r1 = rows[wib][(buf << 2) + 1];
            const float* r2 = rows[wib][(buf << 2) + 2];
            const float* r3 = rows[wib][(buf << 2) + 3];

            float t0 = 0.f, t1 = 0.f, t2 = 0.f, t3 = 0.f;
            #pragma unroll
            for (int g = 0; g < 8; ++g) {
                const float4 f0 = *reinterpret_cast<const float4*>(r0 + (g << 2));
                const float4 f1 = *reinterpret_cast<const float4*>(r1 + (g << 2));
                const float4 f2 = *reinterpret_cast<const float4*>(r2 + (g << 2));
                const float4 f3 = *reinterpret_cast<const float4*>(r3 + (g << 2));
                const float w0 = w[(g << 2) + 0];
                const float w1 = w[(g << 2) + 1];
                const float w2_ = w[(g << 2) + 2];
                const float w3 = w[(g << 2) + 3];
                t0 += f0.x * w0; t0 += f0.y * w1; t0 += f0.z * w2_; t0 += f0.w * w3;
                t1 += f1.x * w0; t1 += f1.y * w1; t1 += f1.z * w2_; t1 += f1.w * w3;
                t2 += f2.x * w0; t2 += f2.y * w1; t2 += f2.z * w2_; t2 += f2.w * w3;
                t3 += f3.x * w0; t3 += f3.y * w1; t3 += f3.z * w2_; t3 += f3.w * w3;
            }

            atomicAdd(&out[e0.x * C + lane], t0);
            atomicAdd(&out[e0.z * C + lane], t1);
            atomicAdd(&out[e1.x * C + lane], t2);
            atomicAdd(&out[e1.z * C + lane], t3);

            // issue quad q+INFLIGHT into buffer consumed at q-1 (WAR safe:
            // one syncwarp/iter bounds lane drift to < 1 iteration)
            const int nx = q + INFLIGHT;
            if (nx < qend) issue_quad(en0, en1, (nx - q0) & (BUFS - 1));
            else           cp_commit();

            if (nx + 1 < qend) {
                en0 = list4[2 * (nx + 1)];
                en1 = list4[2 * (nx + 1) + 1];
            }
        }

        cp_wait<0>();
        __syncwarp();
    }

    // ---- tail (cnt & 3 taps), handled by warp 0 of this k ----
    if (wid_in_k == 0) {
        const int2* list = g_list + k * NCAP;
        for (int t = nquads << 2; t < cnt; ++t) {
            const int2 ent = list[t];
            const float fv = features[(size_t)ent.y * C + lane];
            rows[wib][0][lane] = fv;
            __syncwarp();
            float acc = 0.f;
            #pragma unroll
            for (int g = 0; g < 8; ++g) {
                const float4 f = *reinterpret_cast<const float4*>(rows[wib][0] + (g << 2));
                acc += f.x * w[(g << 2) + 0];
                acc += f.y * w[(g << 2) + 1];
                acc += f.z * w[(g << 2) + 2];
                acc += f.w * w[(g << 2) + 3];
            }
            __syncwarp();
            atomicAdd(&out[ent.x * C + lane], acc);
        }
    }
}

// ---------------------------------------------------------------- launch
extern "C" void kernel_launch(void* const* d_in, const int* in_sizes, int n_in,
                              void* d_out, int out_size)
{
    const float* features = (const float*)d_in[0];
    const float* weight   = (const float*)d_in[1];
    const float* bias     = (const float*)d_in[2];
    const int*   nbr_idx  = (const int*)d_in[3];
    const int*   nbr_mask = (const int*)d_in[4];
    float*       out      = (float*)d_out;

    const int n_sites = in_sizes[0] / C;
    const int n_elems = n_sites * KTAPS;

    zero_kernel<<<1, 32>>>();

    const int cblocks = (n_elems + CB_ELEMS - 1) / CB_ELEMS;
    fused_kernel<<<CEN_BLOCKS + cblocks, FB_THREADS>>>(
        features, weight, bias, nbr_idx, nbr_mask, out, n_sites, n_elems);

    dim3 tgrid(PB_BLOCKS_X, KTAPS - 1);
    taps_kernel<<<tgrid, PB_THREADS>>>(features, weight, out);
}

// round 16
// speedup vs baseline: 1.0506x; 1.0506x over previous
#include <cuda_runtime.h>
#include <cstdint>

// Submanifold sparse conv — compacted per-offset gather-GEMM + PDL overlap.
//  zero_kernel   : reset per-k counters
//  fused_kernel  : blocks [0,CEN_BLOCKS) -> center GEMM (out = bias + F@W13);
//                  rest -> element-parallel compaction. PDL: only the g_count
//                  reservation waits on zero_kernel.
//  taps_kernel   : out[site] += F[nb] @ W[k]; W[k] packed b64 regs; cp.async
//                  4-deep quad pipeline; coalesced atomicAdd epilogue. PDL:
//                  weight prologue runs before waiting on fused.

#define C 32
#define KTAPS 27
#define KCENTER 13
#define NCAP 131072

__device__ int  g_count[KTAPS];
__device__ int2 g_list[KTAPS * NCAP];

typedef unsigned long long u64;

__device__ __forceinline__ u64 fma_f32x2(u64 a, u64 b, u64 c)
{
    u64 d;
    asm("fma.rn.f32x2 %0, %1, %2, %3;" : "=l"(d) : "l"(a), "l"(b), "l"(c));
    return d;
}
__device__ __forceinline__ u64 pack_f32x2(float lo, float hi)
{
    u64 d;
    asm("mov.b64 %0, {%1, %2};" : "=l"(d) : "f"(lo), "f"(hi));
    return d;
}
__device__ __forceinline__ float sum_f32x2(u64 v)
{
    float lo, hi;
    asm("mov.b64 {%0, %1}, %2;" : "=f"(lo), "=f"(hi) : "l"(v));
    return lo + hi;
}
__device__ __forceinline__ void cp_async4(uint32_t saddr, const float* gptr)
{
    asm volatile("cp.async.ca.shared.global [%0], [%1], 4;"
                 :: "r"(saddr), "l"(gptr) : "memory");
}
__device__ __forceinline__ void cp_commit()
{
    asm volatile("cp.async.commit_group;" ::: "memory");
}
template <int N>
__device__ __forceinline__ void cp_wait()
{
    asm volatile("cp.async.wait_group %0;" :: "n"(N) : "memory");
}
__device__ __forceinline__ void grid_dep_sync()
{
    asm volatile("griddepcontrol.wait;" ::: "memory");
}
__device__ __forceinline__ void grid_dep_trigger()
{
    asm volatile("griddepcontrol.launch_dependents;" ::: "memory");
}

// ---------------------------------------------------------------- zero
__global__ void zero_kernel()
{
    if (threadIdx.x < KTAPS) g_count[threadIdx.x] = 0;
}

// ---------------------------------------------------------------- fused center + compact
#define FB_THREADS 256
#define CEN_BLOCKS 592
#define CB_EPT 8
#define CB_ELEMS (FB_THREADS * CB_EPT)

__global__ void __launch_bounds__(FB_THREADS)
fused_kernel(const float* __restrict__ features,
             const float* __restrict__ weight,
             const float* __restrict__ bias,
             const int*   __restrict__ nbr_idx,
             const int*   __restrict__ nbr_mask,
             float* __restrict__ out,
             int n_sites, int n_elems)
{
    __shared__ union {
        struct { int scount[KTAPS]; int sbase[KTAPS]; } cp;
        float rows[FB_THREADS / 32][C];
    } sm;

    const int tid  = threadIdx.x;
    const int lane = tid & 31;
    const int wib  = tid >> 5;

    if (blockIdx.x < CEN_BLOCKS) {
        // ---------------- center GEMM (independent of zero_kernel) ----------
        u64 w2[C / 2];
        const float* w13 = weight + KCENTER * C * C;
        #pragma unroll
        for (int g = 0; g < C / 2; ++g)
            w2[g] = pack_f32x2(w13[(2 * g) * C + lane], w13[(2 * g + 1) * C + lane]);

        const float my_bias = bias[lane];
        float* row = sm.rows[wib];

        const int gwarp  = blockIdx.x * (FB_THREADS / 32) + wib;
        const int nwarps = CEN_BLOCKS * (FB_THREADS / 32);

        float fvA = 0.f;
        if (gwarp < n_sites) fvA = features[gwarp * C + lane];

        for (int site = gwarp; site < n_sites; site += nwarps) {
            const int nsite = site + nwarps;
            float fvB = 0.f;
            if (nsite < n_sites) fvB = features[nsite * C + lane];

            row[lane] = fvA;
            __syncwarp();

            u64 ta = 0ull, tb = 0ull;
            #pragma unroll
            for (int g = 0; g < 8; ++g) {
                const ulonglong2 fp = *reinterpret_cast<const ulonglong2*>(row + (g << 2));
                ta = fma_f32x2(fp.x, w2[2 * g + 0], ta);
                tb = fma_f32x2(fp.y, w2[2 * g + 1], tb);
            }
            __syncwarp();

            out[site * C + lane] = my_bias + sum_f32x2(ta) + sum_f32x2(tb);
            fvA = fvB;
        }
    } else {
        // ---------------- compaction (coalesced) ----------------
        if (tid < KTAPS) sm.cp.scount[tid] = 0;
        __syncthreads();

        const int base = (blockIdx.x - CEN_BLOCKS) * CB_ELEMS;
        bool act[CB_EPT];

        // pass 1: independent of zero_kernel (reads input mask only)
        #pragma unroll
        for (int s = 0; s < CB_EPT; ++s) {
            const int e = base + s * FB_THREADS + tid;
            bool a = false;
            if (e < n_elems) {
                const int k = e % KTAPS;
                a = (k != KCENTER) && (nbr_mask[e] != 0);
                if (a) atomicAdd(&sm.cp.scount[k], 1);
            }
            act[s] = a;
        }
        __syncthreads();

        // reservation touches g_count — must wait for zero_kernel
        grid_dep_sync();
        if (tid < KTAPS) {
            const int c = sm.cp.scount[tid];
            sm.cp.sbase[tid]  = c ? atomicAdd(&g_count[tid], c) : 0;
            sm.cp.scount[tid] = 0;
        }
        __syncthreads();

        #pragma unroll
        for (int s = 0; s < CB_EPT; ++s) {
            if (act[s]) {
                const int e    = base + s * FB_THREADS + tid;
                const int site = e / KTAPS;
                const int k    = e - site * KTAPS;
                const int pos  = sm.cp.sbase[k] + atomicAdd(&sm.cp.scount[k], 1);
                g_list[k * NCAP + pos] = make_int2(site, nbr_idx[e]);
            }
        }
    }
    grid_dep_trigger();
}

// ---------------------------------------------------------------- taps
#define PB_WARPS 8
#define PB_THREADS 256
#define PB_BLOCKS_X 17      // 26*17 = 442 blocks ~= one wave at 3 blocks/SM
#define DEPTH 4             // quads in flight (16 taps)

__global__ void __launch_bounds__(PB_THREADS, 3)
taps_kernel(const float* __restrict__ features,
            const float* __restrict__ weight,
            float* __restrict__ out)
{
    __shared__ float rows[PB_WARPS][DEPTH * 4][C];   // 16 KB
    __shared__ int   ssite[PB_WARPS][DEPTH * 4];

    int k = blockIdx.y;
    if (k >= KCENTER) ++k;

    const int tid  = threadIdx.x;
    const int lane = tid & 31;
    const int wib  = tid >> 5;

    // prologue: weights (input-only) — runs while fused_kernel drains
    u64 w2[C / 2];
    const float* wkp = weight + k * C * C;
    #pragma unroll
    for (int g = 0; g < C / 2; ++g)
        w2[g] = pack_f32x2(wkp[(2 * g) * C + lane], wkp[(2 * g + 1) * C + lane]);

    // from here on we read g_count/g_list/out — wait for fused_kernel
    grid_dep_sync();

    const int cnt    = g_count[k];
    const int nquads = cnt >> 2;
    const int warps_per_k = gridDim.x * PB_WARPS;
    const int wid_in_k = blockIdx.x * PB_WARPS + wib;
    const int chunk = (nquads + warps_per_k - 1) / warps_per_k;
    const int q0   = wid_in_k * chunk;
    const int qend = min(q0 + chunk, nquads);

    const int4* list4 = reinterpret_cast<const int4*>(g_list + k * NCAP);
    const uint32_t rowbase =
        (uint32_t)__cvta_generic_to_shared(&rows[wib][0][0]);

    auto issue_quad = [&](int4 e0, int4 e1, int ph) {
        const uint32_t d = rowbase + (((ph << 2) * C) + lane) * 4u;
        cp_async4(d + 0 * C * 4u, features + (size_t)e0.y * C + lane);
        cp_async4(d + 1 * C * 4u, features + (size_t)e0.w * C + lane);
        cp_async4(d + 2 * C * 4u, features + (size_t)e1.y * C + lane);
        cp_async4(d + 3 * C * 4u, features + (size_t)e1.w * C + lane);
        if (lane == 0) {
            ssite[wib][(ph << 2) + 0] = e0.x;
            ssite[wib][(ph << 2) + 1] = e0.z;
            ssite[wib][(ph << 2) + 2] = e1.x;
            ssite[wib][(ph << 2) + 3] = e1.z;
        }
        cp_commit();
    };

    if (q0 < qend) {
        #pragma unroll
        for (int p = 0; p < DEPTH; ++p) {
            if (q0 + p < qend)
                issue_quad(list4[2 * (q0 + p)], list4[2 * (q0 + p) + 1], p);
            else
                cp_commit();
        }

        int4 en0 = make_int4(0, 0, 0, 0), en1 = en0;
        if (q0 + DEPTH < qend) {
            en0 = list4[2 * (q0 + DEPTH)];
            en1 = list4[2 * (q0 + DEPTH) + 1];
        }

        for (int q = q0; q < qend; ++q) {
            const int ph = (q - q0) & (DEPTH - 1);

            cp_wait<DEPTH - 1>();
            __syncwarp();

            const float* r0 = rows[wib][(ph << 2) + 0];
            const float* r1 = rows[wib][(ph << 2) + 1];
            const float* r2 = rows[wib][(ph << 2) + 2];
            const float* r3 = rows[wib][(ph << 2) + 3];

            u64 t0 = 0ull, t1 = 0ull, t2 = 0ull, t3 = 0ull;
            #pragma unroll
            for (int g = 0; g < 8; ++g) {
                const ulonglong2 f0 = *reinterpret_cast<const ulonglong2*>(r0 + (g << 2));
                const ulonglong2 f1 = *reinterpret_cast<const ulonglong2*>(r1 + (g << 2));
                const ulonglong2 f2 = *reinterpret_cast<const ulonglong2*>(r2 + (g << 2));
                const ulonglong2 f3 = *reinterpret_cast<const ulonglong2*>(r3 + (g << 2));
                const u64 wa = w2[2 * g + 0];
                const u64 wb = w2[2 * g + 1];
                t0 = fma_f32x2(f0.x, wa, t0); t0 = fma_f32x2(f0.y, wb, t0);
                t1 = fma_f32x2(f1.x, wa, t1); t1 = fma_f32x2(f1.y, wb, t1);
                t2 = fma_f32x2(f2.x, wa, t2); t2 = fma_f32x2(f2.y, wb, t2);
                t3 = fma_f32x2(f3.x, wa, t3); t3 = fma_f32x2(f3.y, wb, t3);
            }

            const int s0 = ssite[wib][(ph << 2) + 0];
            const int s1 = ssite[wib][(ph << 2) + 1];
            const int s2 = ssite[wib][(ph << 2) + 2];
            const int s3 = ssite[wib][(ph << 2) + 3];

            atomicAdd(&out[s0 * C + lane], sum_f32x2(t0));
            atomicAdd(&out[s1 * C + lane], sum_f32x2(t1));
            atomicAdd(&out[s2 * C + lane], sum_f32x2(t2));
            atomicAdd(&out[s3 * C + lane], sum_f32x2(t3));

            __syncwarp();

            const int nx = q + DEPTH;
            if (nx < qend) issue_quad(en0, en1, ph);
            else           cp_commit();

            if (nx + 1 < qend) {
                en0 = list4[2 * (nx + 1)];
                en1 = list4[2 * (nx + 1) + 1];
            }
        }

        cp_wait<0>();
        __syncwarp();
    }

    // ---- tail (cnt & 3 taps), handled by warp 0 of this k ----
    if (wid_in_k == 0) {
        const int2* list = g_list + k * NCAP;
        for (int t = nquads << 2; t < cnt; ++t) {
            const int2 ent = list[t];
            const float fv = features[(size_t)ent.y * C + lane];
            rows[wib][0][lane] = fv;
            __syncwarp();
            u64 acc = 0ull;
            #pragma unroll
            for (int g = 0; g < 8; ++g) {
                const ulonglong2 f = *reinterpret_cast<const ulonglong2*>(rows[wib][0] + (g << 2));
                acc = fma_f32x2(f.x, w2[2 * g + 0], acc);
                acc = fma_f32x2(f.y, w2[2 * g + 1], acc);
            }
            __syncwarp();
            atomicAdd(&out[ent.x * C + lane], sum_f32x2(acc));
        }
    }
}

// ---------------------------------------------------------------- launch
extern "C" void kernel_launch(void* const* d_in, const int* in_sizes, int n_in,
                              void* d_out, int out_size)
{
    const float* features = (const float*)d_in[0];
    const float* weight   = (const float*)d_in[1];
    const float* bias     = (const float*)d_in[2];
    const int*   nbr_idx  = (const int*)d_in[3];
    const int*   nbr_mask = (const int*)d_in[4];
    float*       out      = (float*)d_out;

    const int n_sites = in_sizes[0] / C;
    const int n_elems = n_sites * KTAPS;

    zero_kernel<<<1, 32>>>();

    cudaLaunchAttribute attrs[1];
    attrs[0].id = cudaLaunchAttributeProgrammaticStreamSerialization;
    attrs[0].val.programmaticStreamSerializationAllowed = 1;

    // fused: PDL overlap with zero_kernel
    {
        const int cblocks = (n_elems + CB_ELEMS - 1) / CB_ELEMS;
        cudaLaunchConfig_t cfg = {};
        cfg.gridDim  = dim3(CEN_BLOCKS + cblocks, 1, 1);
        cfg.blockDim = dim3(FB_THREADS, 1, 1);
        cfg.attrs    = attrs;
        cfg.numAttrs = 1;
        cudaLaunchKernelEx(&cfg, fused_kernel,
                           features, weight, bias, nbr_idx, nbr_mask, out,
                           n_sites, n_elems);
    }

    // taps: PDL overlap with fused_kernel (weight prologue runs early)
    {
        cudaLaunchConfig_t cfg = {};
        cfg.gridDim  = dim3(PB_BLOCKS_X, KTAPS - 1, 1);
        cfg.blockDim = dim3(PB_THREADS, 1, 1);
        cfg.attrs    = attrs;
        cfg.numAttrs = 1;
        cudaLaunchKernelEx(&cfg, taps_kernel, features, weight, out);
    }
}

// round 17
// speedup vs baseline: 1.1001x; 1.0471x over previous
#include <cuda_runtime.h>
#include <cstdint>

// Submanifold sparse conv — compacted per-offset gather-GEMM + PDL overlap.
//  zero_kernel   : reset per-k counters
//  fused_kernel  : blocks [0,CEN_BLOCKS) -> center GEMM (out = bias + F@W13);
//                  rest -> compaction (coalesced mask+idx prefetch in pass 1,
//                  pass 2 is smem-cursor + STG only). PDL: only the g_count
//                  reservation waits on zero_kernel.
//  taps_kernel   : out[site] += F[nb] @ W[k]; W[k] packed b64 regs; cp.async
//                  4-deep quad pipeline; coalesced atomicAdd epilogue. PDL:
//                  weight prologue runs before waiting on fused.

#define C 32
#define KTAPS 27
#define KCENTER 13
#define NCAP 131072

__device__ int  g_count[KTAPS];
__device__ int2 g_list[KTAPS * NCAP];

typedef unsigned long long u64;

__device__ __forceinline__ u64 fma_f32x2(u64 a, u64 b, u64 c)
{
    u64 d;
    asm("fma.rn.f32x2 %0, %1, %2, %3;" : "=l"(d) : "l"(a), "l"(b), "l"(c));
    return d;
}
__device__ __forceinline__ u64 pack_f32x2(float lo, float hi)
{
    u64 d;
    asm("mov.b64 %0, {%1, %2};" : "=l"(d) : "f"(lo), "f"(hi));
    return d;
}
__device__ __forceinline__ float sum_f32x2(u64 v)
{
    float lo, hi;
    asm("mov.b64 {%0, %1}, %2;" : "=f"(lo), "=f"(hi) : "l"(v));
    return lo + hi;
}
__device__ __forceinline__ void cp_async4(uint32_t saddr, const float* gptr)
{
    asm volatile("cp.async.ca.shared.global [%0], [%1], 4;"
                 :: "r"(saddr), "l"(gptr) : "memory");
}
__device__ __forceinline__ void cp_commit()
{
    asm volatile("cp.async.commit_group;" ::: "memory");
}
template <int N>
__device__ __forceinline__ void cp_wait()
{
    asm volatile("cp.async.wait_group %0;" :: "n"(N) : "memory");
}
__device__ __forceinline__ void grid_dep_sync()
{
    asm volatile("griddepcontrol.wait;" ::: "memory");
}
__device__ __forceinline__ void grid_dep_trigger()
{
    asm volatile("griddepcontrol.launch_dependents;" ::: "memory");
}

// ---------------------------------------------------------------- zero
__global__ void zero_kernel()
{
    if (threadIdx.x < KTAPS) g_count[threadIdx.x] = 0;
}

// ---------------------------------------------------------------- fused center + compact
#define FB_THREADS 256
#define CEN_BLOCKS 592
#define CB_EPT 8
#define CB_ELEMS (FB_THREADS * CB_EPT)

__global__ void __launch_bounds__(FB_THREADS)
fused_kernel(const float* __restrict__ features,
             const float* __restrict__ weight,
             const float* __restrict__ bias,
             const int*   __restrict__ nbr_idx,
             const int*   __restrict__ nbr_mask,
             float* __restrict__ out,
             int n_sites, int n_elems)
{
    __shared__ union {
        struct { int scount[KTAPS]; int sbase[KTAPS]; } cp;
        float rows[FB_THREADS / 32][C];
    } sm;

    const int tid  = threadIdx.x;
    const int lane = tid & 31;
    const int wib  = tid >> 5;

    if (blockIdx.x < CEN_BLOCKS) {
        // ---------------- center GEMM (independent of zero_kernel) ----------
        u64 w2[C / 2];
        const float* w13 = weight + KCENTER * C * C;
        #pragma unroll
        for (int g = 0; g < C / 2; ++g)
            w2[g] = pack_f32x2(w13[(2 * g) * C + lane], w13[(2 * g + 1) * C + lane]);

        const float my_bias = bias[lane];
        float* row = sm.rows[wib];

        const int gwarp  = blockIdx.x * (FB_THREADS / 32) + wib;
        const int nwarps = CEN_BLOCKS * (FB_THREADS / 32);

        float fvA = 0.f;
        if (gwarp < n_sites) fvA = features[gwarp * C + lane];

        for (int site = gwarp; site < n_sites; site += nwarps) {
            const int nsite = site + nwarps;
            float fvB = 0.f;
            if (nsite < n_sites) fvB = features[nsite * C + lane];

            row[lane] = fvA;
            __syncwarp();

            u64 ta = 0ull, tb = 0ull;
            #pragma unroll
            for (int g = 0; g < 8; ++g) {
                const ulonglong2 fp = *reinterpret_cast<const ulonglong2*>(row + (g << 2));
                ta = fma_f32x2(fp.x, w2[2 * g + 0], ta);
                tb = fma_f32x2(fp.y, w2[2 * g + 1], tb);
            }
            __syncwarp();

            out[site * C + lane] = my_bias + sum_f32x2(ta) + sum_f32x2(tb);
            fvA = fvB;
        }
    } else {
        // ---------------- compaction (fully coalesced) ----------------
        if (tid < KTAPS) sm.cp.scount[tid] = 0;
        __syncthreads();

        const int base = (blockIdx.x - CEN_BLOCKS) * CB_ELEMS;
        unsigned actbits = 0;
        int vals[CB_EPT];

        // pass 1: coalesced mask + idx streaming, per-block counts
        #pragma unroll
        for (int s = 0; s < CB_EPT; ++s) {
            const int e = base + s * FB_THREADS + tid;
            vals[s] = 0;
            if (e < n_elems) {
                const int k = e % KTAPS;
                vals[s] = nbr_idx[e];                 // coalesced prefetch
                if (k != KCENTER && nbr_mask[e] != 0) {
                    actbits |= (1u << s);
                    atomicAdd(&sm.cp.scount[k], 1);
                }
            }
        }
        __syncthreads();

        // reservation touches g_count — must wait for zero_kernel
        grid_dep_sync();
        if (tid < KTAPS) {
            const int c = sm.cp.scount[tid];
            sm.cp.sbase[tid]  = c ? atomicAdd(&g_count[tid], c) : 0;
            sm.cp.scount[tid] = 0;
        }
        __syncthreads();

        // pass 2: no global loads — cursor + store only
        #pragma unroll
        for (int s = 0; s < CB_EPT; ++s) {
            if (actbits & (1u << s)) {
                const int e    = base + s * FB_THREADS + tid;
                const int site = e / KTAPS;
                const int k    = e - site * KTAPS;
                const int pos  = sm.cp.sbase[k] + atomicAdd(&sm.cp.scount[k], 1);
                g_list[k * NCAP + pos] = make_int2(site, vals[s]);
            }
        }
    }
    grid_dep_trigger();
}

// ---------------------------------------------------------------- taps
#define PB_WARPS 8
#define PB_THREADS 256
#define PB_BLOCKS_X 17      // 26*17 = 442 blocks ~= one wave at 3 blocks/SM
#define DEPTH 4             // quads in flight (16 taps)

__global__ void __launch_bounds__(PB_THREADS, 3)
taps_kernel(const float* __restrict__ features,
            const float* __restrict__ weight,
            float* __restrict__ out)
{
    __shared__ float rows[PB_WARPS][DEPTH * 4][C];   // 16 KB
    __shared__ int   ssite[PB_WARPS][DEPTH * 4];

    int k = blockIdx.y;
    if (k >= KCENTER) ++k;

    const int tid  = threadIdx.x;
    const int lane = tid & 31;
    const int wib  = tid >> 5;

    // prologue: weights (input-only) — runs while fused_kernel drains
    u64 w2[C / 2];
    const float* wkp = weight + k * C * C;
    #pragma unroll
    for (int g = 0; g < C / 2; ++g)
        w2[g] = pack_f32x2(wkp[(2 * g) * C + lane], wkp[(2 * g + 1) * C + lane]);

    // from here on we read g_count/g_list/out — wait for fused_kernel
    grid_dep_sync();

    const int cnt    = g_count[k];
    const int nquads = cnt >> 2;
    const int warps_per_k = gridDim.x * PB_WARPS;
    const int wid_in_k = blockIdx.x * PB_WARPS + wib;
    const int chunk = (nquads + warps_per_k - 1) / warps_per_k;
    const int q0   = wid_in_k * chunk;
    const int qend = min(q0 + chunk, nquads);

    const int4* list4 = reinterpret_cast<const int4*>(g_list + k * NCAP);
    const uint32_t rowbase =
        (uint32_t)__cvta_generic_to_shared(&rows[wib][0][0]);

    auto issue_quad = [&](int4 e0, int4 e1, int ph) {
        const uint32_t d = rowbase + (((ph << 2) * C) + lane) * 4u;
        cp_async4(d + 0 * C * 4u, features + (size_t)e0.y * C + lane);
        cp_async4(d + 1 * C * 4u, features + (size_t)e0.w * C + lane);
        cp_async4(d + 2 * C * 4u, features + (size_t)e1.y * C + lane);
        cp_async4(d + 3 * C * 4u, features + (size_t)e1.w * C + lane);
        if (lane == 0) {
            ssite[wib][(ph << 2) + 0] = e0.x;
            ssite[wib][(ph << 2) + 1] = e0.z;
            ssite[wib][(ph << 2) + 2] = e1.x;
            ssite[wib][(ph << 2) + 3] = e1.z;
        }
        cp_commit();
    };

    if (q0 < qend) {
        #pragma unroll
        for (int p = 0; p < DEPTH; ++p) {
            if (q0 + p < qend)
                issue_quad(list4[2 * (q0 + p)], list4[2 * (q0 + p) + 1], p);
            else
                cp_commit();
        }

        int4 en0 = make_int4(0, 0, 0, 0), en1 = en0;
        if (q0 + DEPTH < qend) {
            en0 = list4[2 * (q0 + DEPTH)];
            en1 = list4[2 * (q0 + DEPTH) + 1];
        }

        for (int q = q0; q < qend; ++q) {
            const int ph = (q - q0) & (DEPTH - 1);

            cp_wait<DEPTH - 1>();
            __syncwarp();

            const float* r0 = rows[wib][(ph << 2) + 0];
            const float* r1 = rows[wib][(ph << 2) + 1];
            const float* r2 = rows[wib][(ph << 2) + 2];
            const float* r3 = rows[wib][(ph << 2) + 3];

            u64 t0 = 0ull, t1 = 0ull, t2 = 0ull, t3 = 0ull;
            #pragma unroll
            for (int g = 0; g < 8; ++g) {
                const ulonglong2 f0 = *reinterpret_cast<const ulonglong2*>(r0 + (g << 2));
                const ulonglong2 f1 = *reinterpret_cast<const ulonglong2*>(r1 + (g << 2));
                const ulonglong2 f2 = *reinterpret_cast<const ulonglong2*>(r2 + (g << 2));
                const ulonglong2 f3 = *reinterpret_cast<const ulonglong2*>(r3 + (g << 2));
                const u64 wa = w2[2 * g + 0];
                const u64 wb = w2[2 * g + 1];
                t0 = fma_f32x2(f0.x, wa, t0); t0 = fma_f32x2(f0.y, wb, t0);
                t1 = fma_f32x2(f1.x, wa, t1); t1 = fma_f32x2(f1.y, wb, t1);
                t2 = fma_f32x2(f2.x, wa, t2); t2 = fma_f32x2(f2.y, wb, t2);
                t3 = fma_f32x2(f3.x, wa, t3); t3 = fma_f32x2(f3.y, wb, t3);
            }

            const int s0 = ssite[wib][(ph << 2) + 0];
            const int s1 = ssite[wib][(ph << 2) + 1];
            const int s2 = ssite[wib][(ph << 2) + 2];
            const int s3 = ssite[wib][(ph << 2) + 3];

            atomicAdd(&out[s0 * C + lane], sum_f32x2(t0));
            atomicAdd(&out[s1 * C + lane], sum_f32x2(t1));
            atomicAdd(&out[s2 * C + lane], sum_f32x2(t2));
            atomicAdd(&out[s3 * C + lane], sum_f32x2(t3));

            __syncwarp();

            const int nx = q + DEPTH;
            if (nx < qend) issue_quad(en0, en1, ph);
            else           cp_commit();

            if (nx + 1 < qend) {
                en0 = list4[2 * (nx + 1)];
                en1 = list4[2 * (nx + 1) + 1];
            }
        }

        cp_wait<0>();
        __syncwarp();
    }

    // ---- tail (cnt & 3 taps), handled by warp 0 of this k ----
    if (wid_in_k == 0) {
        const int2* list = g_list + k * NCAP;
        for (int t = nquads << 2; t < cnt; ++t) {
            const int2 ent = list[t];
            const float fv = features[(size_t)ent.y * C + lane];
            rows[wib][0][lane] = fv;
            __syncwarp();
            u64 acc = 0ull;
            #pragma unroll
            for (int g = 0; g < 8; ++g) {
                const ulonglong2 f = *reinterpret_cast<const ulonglong2*>(rows[wib][0] + (g << 2));
                acc = fma_f32x2(f.x, w2[2 * g + 0], acc);
                acc = fma_f32x2(f.y, w2[2 * g + 1], acc);
            }
            __syncwarp();
            atomicAdd(&out[ent.x * C + lane], sum_f32x2(acc));
        }
    }
}

// ---------------------------------------------------------------- launch
extern "C" void kernel_launch(void* const* d_in, const int* in_sizes, int n_in,
                              void* d_out, int out_size)
{
    const float* features = (const float*)d_in[0];
    const float* weight   = (const float*)d_in[1];
    const float* bias     = (const float*)d_in[2];
    const int*   nbr_idx  = (const int*)d_in[3];
    const int*   nbr_mask = (const int*)d_in[4];
    float*       out      = (float*)d_out;

    const int n_sites = in_sizes[0] / C;
    const int n_elems = n_sites * KTAPS;

    zero_kernel<<<1, 32>>>();

    cudaLaunchAttribute attrs[1];
    attrs[0].id = cudaLaunchAttributeProgrammaticStreamSerialization;
    attrs[0].val.programmaticStreamSerializationAllowed = 1;

    {
        const int cblocks = (n_elems + CB_ELEMS - 1) / CB_ELEMS;
        cudaLaunchConfig_t cfg = {};
        cfg.gridDim  = dim3(CEN_BLOCKS + cblocks, 1, 1);
        cfg.blockDim = dim3(FB_THREADS, 1, 1);
        cfg.attrs    = attrs;
        cfg.numAttrs = 1;
        cudaLaunchKernelEx(&cfg, fused_kernel,
                           features, weight, bias, nbr_idx, nbr_mask, out,
                           n_sites, n_elems);
    }

    {
        cudaLaunchConfig_t cfg = {};
        cfg.gridDim  = dim3(PB_BLOCKS_X, KTAPS - 1, 1);
        cfg.blockDim = dim3(PB_THREADS, 1, 1);
        cfg.attrs    = attrs;
        cfg.numAttrs = 1;
        cudaLaunchKernelEx(&cfg, taps_kernel, features, weight, out);
    }
}